// round 17
// baseline (speedup 1.0000x reference)
#include <cuda_runtime.h>
#include <cuda_bf16.h>
#include <cuda_fp16.h>
#include <cstdint>

#define NTOK 32768
#define DDIM 256
#define KC   1024
#define HW   1024
#define DECAY_F 0.99f
#define ONE_M_DECAY 0.01f
#define EPS_F 1e-5f
#define CM   16
#define SLACK 0.0625f
#define FP16_MARGIN 1.0f

// output offsets (concatenated float32 outputs in reference return order)
#define O_ZQ   0
#define O_IDX  8388608
#define O_LOSS 8421376
#define O_EMB  8421377
#define O_CS   8683521
#define O_EAVG 8684545

__device__ float g_es[KC * DDIM];
__device__ float g_cs[KC];
__device__ int   g_idx[NTOK];
__device__ float g_enorm[KC];
__device__ float g_p[KC];          // ||e_k||
__device__ float g_q[KC];          // ||e_k - e_k_hi||
__device__ float g_ta[NTOK];       // 2.004*||x - x_hi||
__device__ float g_tb[NTOK];       // 2.004*||x_hi||
__device__ float g_U[NTOK];        // per-token upper bound (from distA, fp32)
__device__ int   g_ccnt[NTOK];
__device__ int   g_cand[NTOK * CM];
__device__ float g_partial[1024];
__device__ float g_n;
__device__ __align__(16) __half g_chat[NTOK * KC];   // hh-GEMM estimates

// A hi-split, mma-FRAGMENT-MAJOR: u32 idx = tblk16*2048 + ks*128 + lane*4 + frag
__device__ __align__(16) uint32_t g_ax0f[NTOK * 128];
// B hi-split row-major (code-major, 512B rows)
__device__ __align__(16) __nv_bfloat16 g_be0[KC * DDIM];

__device__ __forceinline__ uint32_t smem_u32(const void* p) {
    uint32_t a;
    asm("{ .reg .u64 t; cvta.to.shared.u64 t, %1; cvt.u32.u64 %0, t; }"
        : "=r"(a) : "l"(p));
    return a;
}

__device__ __forceinline__ void mma16816(float* c, const uint32_t* a,
                                         uint32_t b0, uint32_t b1) {
    asm volatile(
        "mma.sync.aligned.m16n8k16.row.col.f32.bf16.bf16.f32 "
        "{%0,%1,%2,%3}, {%4,%5,%6,%7}, {%8,%9}, {%0,%1,%2,%3};"
        : "+f"(c[0]), "+f"(c[1]), "+f"(c[2]), "+f"(c[3])
        : "r"(a[0]), "r"(a[1]), "r"(a[2]), "r"(a[3]), "r"(b0), "r"(b1));
}

#define LDSM_X4(r0, r1, r2, r3, addr) \
    asm volatile("ldmatrix.sync.aligned.m8n8.x4.shared.b16 {%0,%1,%2,%3}, [%4];" \
        : "=r"(r0), "=r"(r1), "=r"(r2), "=r"(r3) : "r"(addr))

#define CP_ASYNC16(dst, src) \
    asm volatile("cp.async.cg.shared.global [%0], [%1], 16;" \
                 :: "r"(dst), "l"(src) : "memory")
#define CP_COMMIT() asm volatile("cp.async.commit_group;" ::: "memory")

// ---------------------------------------------------------------------------
// e hi-split + ||e||^2, ||e||, ||delta_e||
// ---------------------------------------------------------------------------
__global__ __launch_bounds__(256) void split_e_kernel(const float* __restrict__ embed) {
    __shared__ float w1[8], w2[8];
    int c = blockIdx.x, tid = threadIdx.x;
    int i = c * DDIM + tid;
    float v = embed[i];
    __nv_bfloat16 h = __float2bfloat16_rn(v);
    g_be0[i] = h;
    float r = v - __bfloat162float(h);
    float s1 = v * v, s2 = r * r;
#pragma unroll
    for (int off = 16; off; off >>= 1) {
        s1 += __shfl_xor_sync(0xffffffffu, s1, off);
        s2 += __shfl_xor_sync(0xffffffffu, s2, off);
    }
    if ((tid & 31) == 0) { w1[tid >> 5] = s1; w2[tid >> 5] = s2; }
    __syncthreads();
    if (tid == 0) {
        float a = 0.f, b = 0.f;
#pragma unroll
        for (int w = 0; w < 8; w++) { a += w1[w]; b += w2[w]; }
        g_enorm[c] = a;
        g_p[c] = sqrtf(a);
        g_q[c] = sqrtf(b);
    }
}

// token-transpose + hi split (fragment-major) + token norms
__global__ __launch_bounds__(256) void split_x_kernel(const float* __restrict__ z) {
    __shared__ float s[32][257];
    __shared__ float pdx[8][32], pxh[8][32];
    int tid = threadIdx.x;
    int t0 = blockIdx.x * 32;
    int bimg = t0 >> 10, hw0 = t0 & 1023;
    int d0 = tid >> 5, ti = tid & 31;
#pragma unroll
    for (int mrow = 0; mrow < 32; mrow++) {
        int d = mrow * 8 + d0;
        s[ti][d] = z[((size_t)bimg * DDIM + d) * HW + hw0 + ti];
    }
    __syncthreads();
    {
        int w = tid >> 5, l = tid & 31;
        float sdx = 0.f, sxh = 0.f;
#pragma unroll
        for (int j = 0; j < 32; j++) {
            int d = w * 32 + j;
            float v = s[l][d];
            float hf = __bfloat162float(__float2bfloat16_rn(v));
            float r = v - hf;
            sdx += r * r;
            sxh += hf * hf;
        }
        pdx[w][l] = sdx; pxh[w][l] = sxh;
    }
    __syncthreads();
    if (tid < 32) {
        float a = 0.f, b = 0.f;
#pragma unroll
        for (int w = 0; w < 8; w++) { a += pdx[w][tid]; b += pxh[w][tid]; }
        g_ta[t0 + tid] = 2.004f * sqrtf(a);
        g_tb[t0 + tid] = 2.004f * sqrtf(b);
    }
    size_t obase = (size_t)(t0 >> 4) * 2048;
#pragma unroll
    for (int i = 0; i < 16; i++) {
        int j = i * 256 + tid;
        int tbl = j >> 11, r = j & 2047;
        int ks = r >> 7, L = (r >> 2) & 31, f = r & 3;
        int g = L >> 2, q = L & 3, half = f & 1, kh = f >> 1;
        int tl = tbl * 16 + half * 8 + g;
        int d = ks * 16 + kh * 8 + q * 2;
        __nv_bfloat16 h0 = __float2bfloat16_rn(s[tl][d]);
        __nv_bfloat16 h1 = __float2bfloat16_rn(s[tl][d + 1]);
        g_ax0f[obase + j] = ((uint32_t)__bfloat16_as_ushort(h1) << 16) | __bfloat16_as_ushort(h0);
    }
}

// ---------------------------------------------------------------------------
// distA: hh GEMM -> g_chat fp16 + per-token U (fp32, fold in epilogue).
// Grid 256 x 128 thr, 2 CTAs/SM. CTA = 128 tokens x 1024 codes, 16 chunks.
// smem: [0,4K) en | [4K,8K) p | [8K,12K) q | [12K, 12K+64K) 2x B buffers
// ---------------------------------------------------------------------------
#define DB_BYTES 32768
#define B_OFF 12288
#define PA_SMEM (B_OFF + 2 * DB_BYTES)

__global__ __launch_bounds__(128, 2) void distA_kernel()
{
    extern __shared__ __align__(1024) char smem[];
    float* s_en = (float*)smem;
    float* s_p  = (float*)(smem + 4096);
    float* s_q  = (float*)(smem + 8192);
    uint32_t sb = smem_u32(smem);
    int tid = threadIdx.x, wid = tid >> 5, lane = tid & 31;
    int t0 = blockIdx.x * 128;
    int group = lane >> 2, tq = lane & 3;
    int bn = (lane & 7) + ((lane >> 4) << 3);
    int bkh = (lane >> 3) & 1;

#pragma unroll
    for (int i = 0; i < 8; i++) {
        int idx = i * 128 + tid;
        s_en[idx] = g_enorm[idx];
        s_p[idx] = g_p[idx];
        s_q[idx] = g_q[idx];
    }

    int trow[4];
    float a4[4], b4[4], minU[4];
#pragma unroll
    for (int mt = 0; mt < 2; mt++)
#pragma unroll
        for (int h = 0; h < 2; h++) {
            int bi = mt * 2 + h;
            trow[bi] = t0 + wid * 32 + mt * 16 + h * 8 + group;
            a4[bi] = g_ta[trow[bi]];
            b4[bi] = g_tb[trow[bi]];
            minU[bi] = 3.4e38f;
        }

    size_t abase[2];
#pragma unroll
    for (int mt = 0; mt < 2; mt++)
        abase[mt] = (size_t)(blockIdx.x * 8 + wid * 2 + mt) * 2048 + lane * 4;

#pragma unroll
    for (int it = 0; it < 16; it++) {
        int id = it * 128 + tid;
        int n = id >> 5, col = id & 31;
        uint32_t dst = sb + B_OFF + n * 512 + ((col ^ (n & 7)) << 4);
        CP_ASYNC16(dst, (const char*)g_be0 + (size_t)n * 512 + col * 16);
    }
    CP_COMMIT();

#pragma unroll 1
    for (int nc = 0; nc < 16; nc++) {
        if (nc < 15) {
            int n0n = (nc + 1) * 64;
            uint32_t bufn = sb + B_OFF + ((nc + 1) & 1) * DB_BYTES;
#pragma unroll
            for (int it = 0; it < 16; it++) {
                int id = it * 128 + tid;
                int n = id >> 5, col = id & 31;
                uint32_t dst = bufn + n * 512 + ((col ^ (n & 7)) << 4);
                CP_ASYNC16(dst, (const char*)g_be0 + (size_t)(n0n + n) * 512 + col * 16);
            }
            CP_COMMIT();
            asm volatile("cp.async.wait_group 1;" ::: "memory");
        } else {
            asm volatile("cp.async.wait_group 0;" ::: "memory");
        }
        __syncthreads();

        uint32_t bbase = sb + B_OFF + (nc & 1) * DB_BYTES;
        float acc[4][2][8];
#pragma unroll
        for (int nt = 0; nt < 4; nt++)
#pragma unroll
            for (int mt = 0; mt < 2; mt++)
#pragma unroll
                for (int j = 0; j < 8; j++) acc[nt][mt][j] = 0.f;

        uint4 acur[2], anxt[2];
#pragma unroll
        for (int mt = 0; mt < 2; mt++)
            acur[mt] = *(const uint4*)(g_ax0f + abase[mt]);

#pragma unroll 1
        for (int ks = 0; ks < 16; ks++) {
            if (ks < 15) {
#pragma unroll
                for (int mt = 0; mt < 2; mt++)
                    anxt[mt] = *(const uint4*)(g_ax0f + abase[mt] + (ks + 1) * 128);
            }
#pragma unroll
            for (int nt = 0; nt < 4; nt++) {
                int nl = nt * 16 + bn;
                uint32_t baddr = bbase + nl * 512 + (((ks * 2 + bkh) ^ (nl & 7)) << 4);
                uint32_t b0, b1, b2, b3;
                LDSM_X4(b0, b1, b2, b3, baddr);
#pragma unroll
                for (int mt = 0; mt < 2; mt++) {
                    mma16816(acc[nt][mt], (const uint32_t*)&acur[mt], b0, b1);
                    mma16816(acc[nt][mt] + 4, (const uint32_t*)&acur[mt], b2, b3);
                }
            }
            acur[0] = anxt[0]; acur[1] = anxt[1];
        }

        // epilogue: store fp16 chat + fold per-token U = min(ch + bd)
        int n0 = nc * 64;
#pragma unroll
        for (int nt = 0; nt < 4; nt++)
#pragma unroll
            for (int mt = 0; mt < 2; mt++) {
                int row0 = t0 + wid * 32 + mt * 16 + group;
#pragma unroll
                for (int nh = 0; nh < 2; nh++) {
                    int cb = n0 + nt * 16 + nh * 8 + tq * 2;
                    const float* c = &acc[nt][mt][nh * 4];
                    *(__half2*)(g_chat + (size_t)row0 * KC + cb) =
                        __floats2half2_rn(c[0], c[1]);
                    *(__half2*)(g_chat + (size_t)(row0 + 8) * KC + cb) =
                        __floats2half2_rn(c[2], c[3]);
                    float2 en = *(const float2*)&s_en[cb];
                    float2 pp = *(const float2*)&s_p[cb];
                    float2 qq = *(const float2*)&s_q[cb];
                    int bi0 = mt * 2, bi1 = mt * 2 + 1;
                    float bd0 = a4[bi0] * pp.x + b4[bi0] * qq.x + SLACK;
                    float bd1 = a4[bi0] * pp.y + b4[bi0] * qq.y + SLACK;
                    float bd2 = a4[bi1] * pp.x + b4[bi1] * qq.x + SLACK;
                    float bd3 = a4[bi1] * pp.y + b4[bi1] * qq.y + SLACK;
                    minU[bi0] = fminf(minU[bi0],
                        fminf(en.x - 2.f * c[0] + bd0, en.y - 2.f * c[1] + bd1));
                    minU[bi1] = fminf(minU[bi1],
                        fminf(en.x - 2.f * c[2] + bd2, en.y - 2.f * c[3] + bd3));
                }
            }
        __syncthreads();
    }

    // quad reduce U (lanes in a quad share token rows; tq varies)
#pragma unroll
    for (int off = 1; off <= 2; off <<= 1)
#pragma unroll
        for (int i = 0; i < 4; i++)
            minU[i] = fminf(minU[i], __shfl_xor_sync(0xffffffffu, minU[i], off));
    if ((lane & 3) == 0) {
#pragma unroll
        for (int i = 0; i < 4; i++) g_U[trow[i]] = minU[i];
    }
}

// ---------------------------------------------------------------------------
// collect: warp per token, single pass. Test: f - 2c <= thr2,
// f = en - a*p - b*q (2 FMA/code), thr2 = U + FP16_MARGIN + SLACK.
// ---------------------------------------------------------------------------
__global__ __launch_bounds__(256) void collect_kernel()
{
    __shared__ float sp[KC], sq[KC], sen[KC];
    int tid = threadIdx.x, wid = tid >> 5, lane = tid & 31;
    for (int i = tid; i < KC; i += 256) {
        sp[i] = g_p[i]; sq[i] = g_q[i]; sen[i] = g_enorm[i];
    }
    __syncthreads();

    int t = blockIdx.x * 8 + wid;
    float a = g_ta[t], b = g_tb[t];
    float thr2 = g_U[t] + FP16_MARGIN + SLACK;
    const __half2* ch = (const __half2*)(g_chat + (size_t)t * KC);

    int cnt = 0;
    unsigned lmask = (1u << lane) - 1u;
#pragma unroll
    for (int j = 0; j < 16; j++) {
        __half2 v = ch[j * 32 + lane];
        int k0 = (j * 32 + lane) * 2;
        float2 c2 = __half22float2(v);
        float f0 = sen[k0] - (a * sp[k0] + b * sq[k0]);
        float f1 = sen[k0 + 1] - (a * sp[k0 + 1] + b * sq[k0 + 1]);
        bool p0 = (f0 - 2.f * c2.x <= thr2);
        bool p1 = (f1 - 2.f * c2.y <= thr2);
        unsigned m0 = __ballot_sync(0xffffffffu, p0);
        if (p0) {
            int pos = cnt + __popc(m0 & lmask);
            if (pos < CM) g_cand[t * CM + pos] = k0;
        }
        cnt += __popc(m0);
        unsigned m1 = __ballot_sync(0xffffffffu, p1);
        if (p1) {
            int pos = cnt + __popc(m1 & lmask);
            if (pos < CM) g_cand[t * CM + pos] = k0 + 1;
        }
        cnt += __popc(m1);
    }
    if (lane == 0) g_ccnt[t] = cnt;
}

// ---------------------------------------------------------------------------
// Fused resolve + gather (R16-verified). Block = 32 tokens, 256 thr.
// ---------------------------------------------------------------------------
#define RG_SMEM ((32 * 257 + 256 * 33) * 4)

__global__ __launch_bounds__(256) void resolve_gather_kernel(
    const float* __restrict__ z, const float* __restrict__ embed,
    float* __restrict__ out)
{
    extern __shared__ float dsm[];
    float (*sZ)[257] = (float (*)[257])dsm;                 // [32][257]
    float (*sE)[33]  = (float (*)[33])(dsm + 32 * 257);     // [256][33]
    __shared__ int   kidx[32];
    __shared__ float wred[8];
    int tid = threadIdx.x, wid = tid >> 5, lane = tid & 31;
    int t0 = blockIdx.x * 32;
    int bimg = t0 >> 10, hw0 = t0 & 1023;

    {
        int d0 = tid >> 5, ti = tid & 31;
#pragma unroll
        for (int mrow = 0; mrow < 32; mrow++) {
            int d = mrow * 8 + d0;
            sZ[ti][d] = z[((size_t)bimg * DDIM + d) * HW + hw0 + ti];
        }
    }
    __syncthreads();

#pragma unroll 1
    for (int it = 0; it < 4; it++) {
        int lt = wid * 4 + it;
        int t = t0 + lt;
        float x[8];
#pragma unroll
        for (int j = 0; j < 8; j++) x[j] = sZ[lt][lane * 8 + j];
        int cnt = g_ccnt[t];
        float best = 3.4e38f;
        int bk = 0;
        bool fallback = (cnt > CM) || (cnt == 0);
        int niter = fallback ? KC : cnt;
        for (int i = 0; i < niter; i++) {
            int k = fallback ? i : g_cand[t * CM + i];
            const float* er = embed + (size_t)k * DDIM + lane * 8;
            float4 e0 = *(const float4*)er;
            float4 e1 = *(const float4*)(er + 4);
            float s = x[0] * e0.x + x[1] * e0.y + x[2] * e0.z + x[3] * e0.w
                    + x[4] * e1.x + x[5] * e1.y + x[6] * e1.z + x[7] * e1.w;
#pragma unroll
            for (int off = 16; off; off >>= 1) s += __shfl_xor_sync(0xffffffffu, s, off);
            float c = g_enorm[k] - 2.f * s;
            if (c < best || (c == best && k < bk)) { best = c; bk = k; }
        }
        if (lane == 0) {
            kidx[lt] = bk;
            g_idx[t] = bk;
            out[O_IDX + t] = (float)bk;
            atomicAdd(&g_cs[bk], 1.0f);
        }
    }
    __syncthreads();

#pragma unroll
    for (int l = 0; l < 32; l++)
        sE[tid][l] = embed[(size_t)kidx[l] * DDIM + tid];
    __syncthreads();

    int ti = tid & 31, dq = (tid >> 5) * 4;
    int myk = kidx[ti];
    float* esrow = &g_es[(size_t)myk * DDIM];
    float lsum = 0.f;
    float* ob = out + O_ZQ + (size_t)bimg * DDIM * HW + hw0 + ti;
#pragma unroll
    for (int m = 0; m < 8; m++) {
        int d = m * 32 + dq;
        float e0 = sE[d][ti], e1 = sE[d + 1][ti], e2 = sE[d + 2][ti], e3 = sE[d + 3][ti];
        float z0 = sZ[ti][d], z1 = sZ[ti][d + 1], z2 = sZ[ti][d + 2], z3 = sZ[ti][d + 3];
        size_t zo = (size_t)d * HW;
        ob[zo] = e0; ob[zo + HW] = e1; ob[zo + 2 * HW] = e2; ob[zo + 3 * HW] = e3;
        float f0 = z0 - e0, f1 = z1 - e1, f2 = z2 - e2, f3 = z3 - e3;
        lsum += f0 * f0 + f1 * f1 + f2 * f2 + f3 * f3;
        asm volatile("red.global.add.v4.f32 [%0], {%1, %2, %3, %4};"
                     :: "l"(esrow + d), "f"(z0), "f"(z1), "f"(z2), "f"(z3) : "memory");
    }
#pragma unroll
    for (int off = 16; off; off >>= 1) lsum += __shfl_xor_sync(0xffffffffu, lsum, off);
    if ((tid & 31) == 0) wred[tid >> 5] = lsum;
    __syncthreads();
    if (tid == 0) {
        float s = 0.f;
#pragma unroll
        for (int w = 0; w < 8; w++) s += wred[w];
        g_partial[blockIdx.x] = s;
    }
}

// loss finalize + EMA cluster-size + n (single block)
__global__ void ema_a_kernel(const float* __restrict__ cluster_size,
                             float* __restrict__ out) {
    __shared__ float red[KC];
    __shared__ float red2[KC];
    int k = threadIdx.x;
    float ncs = cluster_size[k] * DECAY_F + ONE_M_DECAY * g_cs[k];
    out[O_CS + k] = ncs;
    red[k] = ncs;
    red2[k] = g_partial[k];
    __syncthreads();
    for (int off = 512; off; off >>= 1) {
        if (k < off) { red[k] += red[k + off]; red2[k] += red2[k + off]; }
        __syncthreads();
    }
    if (k == 0) { g_n = red[0]; out[O_LOSS] = red2[0] / 8388608.0f; }
}

__global__ void ema_b_kernel(const float* __restrict__ embed_avg,
                             float* __restrict__ out) {
    int idx = blockIdx.x * 256 + threadIdx.x;
    int k = idx >> 8;
    float nea = embed_avg[idx] * DECAY_F + ONE_M_DECAY * g_es[idx];
    out[O_EAVG + idx] = nea;
    float ncs = out[O_CS + k];
    float n = g_n;
    float csn = (ncs + EPS_F) / (n + KC * EPS_F) * n;
    out[O_EMB + idx] = nea / csn;
}

// ---------------------------------------------------------------------------
extern "C" void kernel_launch(void* const* d_in, const int* in_sizes, int n_in,
                              void* d_out, int out_size)
{
    const float* z            = (const float*)d_in[0];
    const float* embed        = (const float*)d_in[1];
    const float* cluster_size = (const float*)d_in[2];
    const float* embed_avg    = (const float*)d_in[3];
    float* out = (float*)d_out;

    cudaFuncSetAttribute(distA_kernel,
                         cudaFuncAttributeMaxDynamicSharedMemorySize, PA_SMEM);
    cudaFuncSetAttribute(resolve_gather_kernel,
                         cudaFuncAttributeMaxDynamicSharedMemorySize, RG_SMEM);

    void* p;
    cudaGetSymbolAddress(&p, g_es);
    cudaMemsetAsync(p, 0, KC * DDIM * sizeof(float));          // launch 1
    cudaGetSymbolAddress(&p, g_cs);
    cudaMemsetAsync(p, 0, KC * sizeof(float));                 // launch 2

    split_e_kernel<<<KC, 256>>>(embed);                        // launch 3
    split_x_kernel<<<NTOK / 32, 256>>>(z);                     // launch 4
    distA_kernel<<<NTOK / 128, 128, PA_SMEM>>>();              // launch 5
    collect_kernel<<<NTOK / 8, 256>>>();                       // launch 6 <- ncu
    resolve_gather_kernel<<<NTOK / 32, 256, RG_SMEM>>>(z, embed, out);  // launch 7
    ema_a_kernel<<<1, KC>>>(cluster_size, out);                // launch 8
    ema_b_kernel<<<KC * DDIM / 256, 256>>>(embed_avg, out);    // launch 9
}